// round 15
// baseline (speedup 1.0000x reference)
#include <cuda_runtime.h>
#include <cuda_fp16.h>
#include <cstdint>

// ============================================================================
// GraphSAGE fused layer — sm_103 baseline-PTX, warp-specialized pipeline (R11).
//
//   out = relu(concat(feature[nodes], mean(feature[neigh_idx],1)) @ W)
//   B=50000, S=10, D=128, H=128, K=256.
//
// R11 delta vs R10 (35.3us, occ 35%, L1 57%, still producer-latency bound):
//   BLK_M 32 -> 64.
//   * producer MLP 22 -> 44 outstanding loads/warp (near the ~55 cap)
//   * tile count halves (782) => barrier handshake overhead halves
//   * all 8 consumer warps work every tile (no even/odd groups), 32x32 warp
//     tiles in a 2x4 grid over the 64x128 stage
//   * NSTAGE=3 x 32KB + 64KB weights = 160KB smem
// ============================================================================

static constexpr int BLK_M   = 64;
static constexpr int K_DIM   = 256;
static constexpr int H_OUT   = 128;
static constexpr int S_NEIGH = 10;
static constexpr int ROW_B   = 512;                   // 256 fp16, swizzled
static constexpr int W_BYTES = H_OUT * ROW_B;         // 65536
static constexpr int A_STAGE = BLK_M * ROW_B;         // 32768
static constexpr int NSTAGE  = 3;
static constexpr int N_THREADS = 768;

// smem layout
static constexpr int SM_W     = 0;
static constexpr int SM_A     = SM_W + W_BYTES;           // 65536
static constexpr int SM_BAR   = SM_A + NSTAGE * A_STAGE;  // 163840
static constexpr int SM_TOTAL = SM_BAR + 80;

__device__ __align__(16) unsigned char g_wh[W_BYTES];

// ---------------- helpers ----------------
__device__ __forceinline__ uint32_t smem_u32(const void* p) {
    uint32_t a;
    asm("{ .reg .u64 t; cvta.to.shared.u64 t, %1; cvt.u32.u64 %0, t; }"
        : "=r"(a) : "l"(p));
    return a;
}

// swizzled byte offset for element (row, kcol) in a 512B-pitch fp16 tile:
// 16B chunk index XORed with row%8
__host__ __device__ __forceinline__ uint32_t sw_off(int row, int kcol) {
    uint32_t byte  = (uint32_t)kcol * 2u;
    uint32_t chunk = (byte >> 4) ^ ((uint32_t)row & 7u);
    return (uint32_t)row * ROW_B + (chunk << 4) + (byte & 15u);
}

__device__ __forceinline__ void ldsm_x4(uint32_t (&d)[4], uint32_t addr) {
    asm volatile("ldmatrix.sync.aligned.m8n8.x4.shared.b16 {%0,%1,%2,%3}, [%4];"
                 : "=r"(d[0]), "=r"(d[1]), "=r"(d[2]), "=r"(d[3]) : "r"(addr));
}

__device__ __forceinline__ void mma_f16(float (&c)[4], const uint32_t (&a)[4],
                                        uint32_t b0, uint32_t b1) {
    asm volatile(
        "mma.sync.aligned.m16n8k16.row.col.f32.f16.f16.f32 "
        "{%0,%1,%2,%3}, {%4,%5,%6,%7}, {%8,%9}, {%0,%1,%2,%3};"
        : "+f"(c[0]), "+f"(c[1]), "+f"(c[2]), "+f"(c[3])
        : "r"(a[0]), "r"(a[1]), "r"(a[2]), "r"(a[3]), "r"(b0), "r"(b1));
}

#define MBARRIER_INIT(mbar, count) \
    asm volatile("mbarrier.init.shared.b64 [%0], %1;" \
                 :: "r"((uint32_t)(mbar)), "r"((uint32_t)(count)) : "memory")

#define MBARRIER_ARRIVE(mbar) \
    asm volatile("mbarrier.arrive.shared.b64 _, [%0];" \
                 :: "r"((uint32_t)(mbar)) : "memory")

#define MBARRIER_WAIT_PARITY(mbar, parity) do {                                  \
    uint32_t _m = (uint32_t)(mbar); uint32_t _p = (uint32_t)(parity);            \
    asm volatile(                                                                \
        "{\n\t.reg .pred P1;\n\t"                                                \
        "WAIT_LOOP_%=:\n\t"                                                      \
        "mbarrier.try_wait.parity.shared.b64 P1, [%0], %1;\n\t"                  \
        "@P1 bra.uni WAIT_DONE_%=;\n\t"                                          \
        "bra.uni WAIT_LOOP_%=;\n\t"                                              \
        "WAIT_DONE_%=:\n\t}"                                                     \
        :: "r"(_m), "r"(_p) : "memory");                                         \
} while (0)

#define FULL_BAR(sb, s)  ((sb) + SM_BAR + (s) * 16)
#define EMPTY_BAR(sb, s) ((sb) + SM_BAR + (s) * 16 + 8)

// ---------------- weight prep: transpose + fp16 + swizzle --------------------
__global__ void sage_prep_weight(const float* __restrict__ w) {
    int i = blockIdx.x * blockDim.x + threadIdx.x;
    if (i >= K_DIM * H_OUT) return;
    int k = i >> 7;        // weight row (0..255)
    int n = i & 127;       // weight col (0..127)
    *reinterpret_cast<__half*>(g_wh + sw_off(n, k)) = __float2half_rn(w[i]);
}

// ---------------- fused persistent warp-specialized kernel -------------------
__global__ __launch_bounds__(N_THREADS, 1)
void sage_main(const int* __restrict__ nodes,
               const int* __restrict__ neigh,
               const float* __restrict__ feat,
               float* __restrict__ out,
               int B, int ntiles) {
    extern __shared__ __align__(16) char smem[];
    const uint32_t sb   = smem_u32(smem);
    const int tid  = threadIdx.x;
    const int wid  = tid >> 5;
    const int lane = tid & 31;

    if (tid == 0) {
        #pragma unroll
        for (int s = 0; s < NSTAGE; s++) {
            MBARRIER_INIT(FULL_BAR(sb, s), 512);   // 16 producer warps arrive
            MBARRIER_INIT(EMPTY_BAR(sb, s), 256);  // 8 consumer warps arrive
        }
    }

    // copy weight into smem once (swizzle preserved by linear copy)
    {
        const uint4* s0 = reinterpret_cast<const uint4*>(g_wh);
        uint4* d0 = reinterpret_cast<uint4*>(smem + SM_W);
        for (int i = tid; i < W_BYTES / 16; i += N_THREADS) d0[i] = s0[i];
    }
    __syncthreads();

    if (wid < 16) {
        // ============ PRODUCERS: 16 warps, 4 rows each, fp32 gather ============
        // lane l covers cols 4l..4l+3 of a feature row (float4)
        const float4* feat4 = reinterpret_cast<const float4*>(feat);
        int stage = 0;
        uint32_t eph = 0x7u;   // per-stage empty parities (first pass free)

        // prologue: indices for first tile
        int selfi[4], idxv[4];
        {
            const int base = blockIdx.x * BLK_M;
            #pragma unroll
            for (int i = 0; i < 4; i++) {
                const int grow = base + wid * 4 + i;
                const int src = (grow < B) ? grow : 0;
                selfi[i] = __ldg(nodes + src);
                idxv[i] = (lane < S_NEIGH)
                          ? __ldg(neigh + (size_t)src * S_NEIGH + lane) : 0;
            }
        }

        for (int tile = blockIdx.x; tile < ntiles; tile += gridDim.x) {
            // --- feature loads for current tile (indices already resident) ---
            float4 sv[4], acc[4];
            #pragma unroll
            for (int i = 0; i < 4; i++) {
                sv[i] = __ldg(feat4 + (size_t)selfi[i] * 32 + lane);
                acc[i] = make_float4(0.f, 0.f, 0.f, 0.f);
            }

            // --- prefetch next tile's indices (hidden behind feature loads) ---
            int nselfi[4], nidxv[4];
            {
                const long nt = (long)tile + gridDim.x;
                const int nbase = (nt < ntiles) ? (int)nt * BLK_M : 0;
                #pragma unroll
                for (int i = 0; i < 4; i++) {
                    const int grow = nbase + wid * 4 + i;
                    const int src = (grow < B) ? grow : 0;
                    nselfi[i] = __ldg(nodes + src);
                    nidxv[i] = (lane < S_NEIGH)
                               ? __ldg(neigh + (size_t)src * S_NEIGH + lane) : 0;
                }
            }

            #pragma unroll
            for (int s = 0; s < S_NEIGH; s++) {
                #pragma unroll
                for (int i = 0; i < 4; i++) {
                    const int ni = __shfl_sync(0xffffffffu, idxv[i], s);
                    const float4 v = __ldg(feat4 + (size_t)ni * 32 + lane);
                    acc[i].x += v.x; acc[i].y += v.y;
                    acc[i].z += v.z; acc[i].w += v.w;
                }
            }

            // --- claim the stage buffer only now ---
            MBARRIER_WAIT_PARITY(EMPTY_BAR(sb, stage), (eph >> stage) & 1u);
            eph ^= (1u << stage);

            const uint32_t aT = sb + SM_A + stage * A_STAGE;

            #pragma unroll
            for (int i = 0; i < 4; i++) {
                const int r = wid * 4 + i;
                // self part (cols 4l..4l+3)
                __half2 s0 = __floats2half2_rn(sv[i].x, sv[i].y);
                __half2 s1 = __floats2half2_rn(sv[i].z, sv[i].w);
                const uint32_t sx = *reinterpret_cast<uint32_t*>(&s0);
                const uint32_t sy = *reinterpret_cast<uint32_t*>(&s1);
                asm volatile("st.shared.v2.b32 [%0], {%1, %2};"
                             :: "r"(aT + sw_off(r, 4 * lane)), "r"(sx), "r"(sy)
                             : "memory");
                // neighbor mean part (cols 128 + 4l ..)
                __half2 p0 = __floats2half2_rn(acc[i].x * 0.1f, acc[i].y * 0.1f);
                __half2 p1 = __floats2half2_rn(acc[i].z * 0.1f, acc[i].w * 0.1f);
                const uint32_t m0 = *reinterpret_cast<uint32_t*>(&p0);
                const uint32_t m1 = *reinterpret_cast<uint32_t*>(&p1);
                asm volatile("st.shared.v2.b32 [%0], {%1, %2};"
                             :: "r"(aT + sw_off(r, 128 + 4 * lane)), "r"(m0), "r"(m1)
                             : "memory");
            }

            __threadfence_block();
            MBARRIER_ARRIVE(FULL_BAR(sb, stage));
            stage = (stage == NSTAGE - 1) ? 0 : stage + 1;

            #pragma unroll
            for (int i = 0; i < 4; i++) { selfi[i] = nselfi[i]; idxv[i] = nidxv[i]; }
        }
    } else {
        // ============ CONSUMERS: 8 warps, 32x32 tiles in a 2x4 grid ============
        const int cw  = wid - 16;           // 0..7
        const int mr  = (cw & 1) * 32;      // 0 or 32
        const int nc  = (cw >> 1) * 32;     // 0,32,64,96
        const uint32_t sW = sb + SM_W;

        const uint32_t a_row = (uint32_t)(mr + (lane & 15));
        const uint32_t a_sel = (uint32_t)(lane >> 4);          // 0/1
        const uint32_t b_row = (uint32_t)(nc + (lane & 7) + ((lane & 16) >> 1));
        const uint32_t b_sel = (uint32_t)((lane >> 3) & 1);    // 0/1
        const uint32_t a_x   = a_row & 7u;
        const uint32_t b_x   = b_row & 7u;
        const uint32_t aRowB = a_row * ROW_B;
        const uint32_t bRowB = b_row * ROW_B;

        int stage = 0;
        uint32_t cph = 0u;    // per-stage full parities

        for (int tile = blockIdx.x; tile < ntiles; tile += gridDim.x) {
            const int base = tile * BLK_M;

            MBARRIER_WAIT_PARITY(FULL_BAR(sb, stage), (cph >> stage) & 1u);
            cph ^= (1u << stage);

            const uint32_t aT = sb + SM_A + stage * A_STAGE;

            float acc[2][4][4];
            #pragma unroll
            for (int m = 0; m < 2; m++)
                #pragma unroll
                for (int n = 0; n < 4; n++)
                    #pragma unroll
                    for (int j = 0; j < 4; j++) acc[m][n][j] = 0.f;

            #pragma unroll
            for (int k = 0; k < K_DIM / 16; k++) {
                const uint32_t ac = (((2u * k + a_sel) ^ a_x) << 4);
                const uint32_t bc = (((2u * k + b_sel) ^ b_x) << 4);

                uint32_t a0[4], a1[4];
                ldsm_x4(a0, aT + aRowB + ac);
                ldsm_x4(a1, aT + aRowB + ac + 16 * ROW_B);

                uint32_t b0[4], b1[4];
                ldsm_x4(b0, sW + bRowB + bc);
                ldsm_x4(b1, sW + bRowB + bc + 16 * ROW_B);

                mma_f16(acc[0][0], a0, b0[0], b0[1]);
                mma_f16(acc[0][1], a0, b0[2], b0[3]);
                mma_f16(acc[0][2], a0, b1[0], b1[1]);
                mma_f16(acc[0][3], a0, b1[2], b1[3]);
                mma_f16(acc[1][0], a1, b0[0], b0[1]);
                mma_f16(acc[1][1], a1, b0[2], b0[3]);
                mma_f16(acc[1][2], a1, b1[0], b1[1]);
                mma_f16(acc[1][3], a1, b1[2], b1[3]);
            }

            MBARRIER_ARRIVE(EMPTY_BAR(sb, stage));
            stage = (stage == NSTAGE - 1) ? 0 : stage + 1;

            // epilogue from registers (stage already released)
            #pragma unroll
            for (int mi = 0; mi < 2; mi++) {
                const int r0 = base + mr + mi * 16 + (lane >> 2);
                #pragma unroll
                for (int nt = 0; nt < 4; nt++) {
                    const int c = nc + nt * 8 + 2 * (lane & 3);
                    if (r0 < B) {
                        float2 v;
                        v.x = fmaxf(acc[mi][nt][0], 0.f);
                        v.y = fmaxf(acc[mi][nt][1], 0.f);
                        *reinterpret_cast<float2*>(out + (size_t)r0 * H_OUT + c) = v;
                    }
                    if (r0 + 8 < B) {
                        float2 v;
                        v.x = fmaxf(acc[mi][nt][2], 0.f);
                        v.y = fmaxf(acc[mi][nt][3], 0.f);
                        *reinterpret_cast<float2*>(out + (size_t)(r0 + 8) * H_OUT + c) = v;
                    }
                }
            }
        }
    }
}

// ---------------- launch ------------------------------------------------------
extern "C" void kernel_launch(void* const* d_in, const int* in_sizes, int n_in,
                              void* d_out, int out_size) {
    const int*   nodes  = (const int*)d_in[0];
    const int*   neigh  = (const int*)d_in[1];
    const float* feat   = (const float*)d_in[2];
    const float* weight = (const float*)d_in[3];
    float*       out    = (float*)d_out;
    const int B = in_sizes[0];
    const int ntiles = (B + BLK_M - 1) / BLK_M;

    sage_prep_weight<<<(K_DIM * H_OUT + 255) / 256, 256>>>(weight);

    cudaFuncSetAttribute(sage_main, cudaFuncAttributeMaxDynamicSharedMemorySize, SM_TOTAL);
    const int grid = (ntiles < 148) ? ntiles : 148;
    sage_main<<<grid, N_THREADS, SM_TOTAL>>>(nodes, neigh, feat, out, B, ntiles);
}